// round 3
// baseline (speedup 1.0000x reference)
#include <cuda_runtime.h>
#include <math.h>

#define BATCH   16
#define HEADS   32
#define HDIM    128
#define NBLK    1024
#define BLKSZ   16
#define MAXB    128
#define HIDDEN  (HEADS * HDIM)
#define EPS     1e-6f
#define SCALE   0.08838834764831845f   // 1/sqrt(128)
#define NWARP   8

// scratch for normalized q (allocation-free per harness rules)
__device__ float g_q[BATCH * HIDDEN];

// ---------------------------------------------------------------------------
// Kernel 1: RMSNorm  q = x * rsqrt(mean(x^2)+eps) * w
// ---------------------------------------------------------------------------
__global__ void rmsnorm_kernel(const float* __restrict__ x,
                               const float* __restrict__ w) {
    const int b = blockIdx.x;
    const float4* row = (const float4*)(x + b * HIDDEN);
    const float4* wt  = (const float4*)w;
    float4* qo = (float4*)(g_q + b * HIDDEN);

    // 256 threads, HIDDEN/4 = 1024 float4 -> 4 per thread
    float ss = 0.f;
    float4 v[4];
    #pragma unroll
    for (int i = 0; i < 4; i++) {
        v[i] = row[threadIdx.x + i * 256];
        ss += v[i].x * v[i].x + v[i].y * v[i].y + v[i].z * v[i].z + v[i].w * v[i].w;
    }
    #pragma unroll
    for (int o = 16; o; o >>= 1) ss += __shfl_xor_sync(~0u, ss, o);

    __shared__ float red[8];
    if ((threadIdx.x & 31) == 0) red[threadIdx.x >> 5] = ss;
    __syncthreads();
    if (threadIdx.x < 32) {
        float s = (threadIdx.x < 8) ? red[threadIdx.x] : 0.f;
        #pragma unroll
        for (int o = 4; o; o >>= 1) s += __shfl_xor_sync(~0u, s, o);
        if (threadIdx.x == 0) red[0] = s;
    }
    __syncthreads();
    const float inv = rsqrtf(red[0] * (1.0f / HIDDEN) + EPS);

    #pragma unroll
    for (int i = 0; i < 4; i++) {
        float4 g = wt[threadIdx.x + i * 256];
        float4 o;
        o.x = v[i].x * inv * g.x;
        o.y = v[i].y * inv * g.y;
        o.z = v[i].z * inv * g.z;
        o.w = v[i].w * inv * g.w;
        qo[threadIdx.x + i * 256] = o;
    }
}

// ---------------------------------------------------------------------------
// Kernel 2: paged flash-decode, one CTA per (head, batch)
// 8 warps; warp w handles tokens w, w+8, w+16, ...  (2-token unroll)
// lane l owns head-dim elements [4l, 4l+4) as a float4
// ---------------------------------------------------------------------------
__global__ __launch_bounds__(256, 4)
void attn_kernel(const float* __restrict__ kc,
                 const float* __restrict__ vc,
                 const int*   __restrict__ bt,
                 const int*   __restrict__ ctx,
                 const float* __restrict__ hidden,
                 float*       __restrict__ out) {
    const int h = blockIdx.x;
    const int b = blockIdx.y;
    const int tid  = threadIdx.x;
    const int lane = tid & 31;
    const int warp = tid >> 5;

    __shared__ float4 sq[HDIM / 4];
    __shared__ int    sbt[MAXB];
    __shared__ float  sm_m[NWARP], sm_l[NWARP];
    __shared__ float4 sm_acc[NWARP][HDIM / 4];

    if (tid < HDIM / 4) sq[tid] = ((const float4*)(g_q + b * HIDDEN + h * HDIM))[tid];
    if (tid < MAXB)     sbt[tid] = bt[b * MAXB + tid];
    __syncthreads();

    const int   L  = ctx[b];
    const float4 q4 = sq[lane];

    float  m = -INFINITY, l = 0.f;
    float4 acc = make_float4(0.f, 0.f, 0.f, 0.f);

    int s = warp;
    // main loop: 2 tokens per iteration -> 4 independent LDG.128 in flight
    for (; s + NWARP < L; s += 2 * NWARP) {
        const int sa = s, sb2 = s + NWARP;
        const size_t offa = (((size_t)sbt[sa  >> 4] * BLKSZ + (sa  & 15)) * HEADS + h) * HDIM;
        const size_t offb = (((size_t)sbt[sb2 >> 4] * BLKSZ + (sb2 & 15)) * HEADS + h) * HDIM;
        float4 ka = ((const float4*)(kc + offa))[lane];
        float4 kb = ((const float4*)(kc + offb))[lane];
        float4 va = ((const float4*)(vc + offa))[lane];
        float4 vb = ((const float4*)(vc + offb))[lane];

        float da = q4.x * ka.x + q4.y * ka.y + q4.z * ka.z + q4.w * ka.w;
        float db = q4.x * kb.x + q4.y * kb.y + q4.z * kb.z + q4.w * kb.w;
        #pragma unroll
        for (int o = 16; o; o >>= 1) {
            da += __shfl_xor_sync(~0u, da, o);
            db += __shfl_xor_sync(~0u, db, o);
        }
        const float s0 = da * SCALE;
        const float s1 = db * SCALE;

        const float m_new = fmaxf(m, fmaxf(s0, s1));
        const float corr  = __expf(m - m_new);
        const float p0    = __expf(s0 - m_new);
        const float p1    = __expf(s1 - m_new);
        l = l * corr + p0 + p1;
        acc.x = acc.x * corr + p0 * va.x + p1 * vb.x;
        acc.y = acc.y * corr + p0 * va.y + p1 * vb.y;
        acc.z = acc.z * corr + p0 * va.z + p1 * vb.z;
        acc.w = acc.w * corr + p0 * va.w + p1 * vb.w;
        m = m_new;
    }
    // tail: at most one token left for this warp
    if (s < L) {
        const size_t off = (((size_t)sbt[s >> 4] * BLKSZ + (s & 15)) * HEADS + h) * HDIM;
        float4 k4 = ((const float4*)(kc + off))[lane];
        float4 v4 = ((const float4*)(vc + off))[lane];
        float d = q4.x * k4.x + q4.y * k4.y + q4.z * k4.z + q4.w * k4.w;
        #pragma unroll
        for (int o = 16; o; o >>= 1) d += __shfl_xor_sync(~0u, d, o);
        const float sc = d * SCALE;
        const float m_new = fmaxf(m, sc);
        const float corr  = __expf(m - m_new);
        const float p     = __expf(sc - m_new);
        l = l * corr + p;
        acc.x = acc.x * corr + p * v4.x;
        acc.y = acc.y * corr + p * v4.y;
        acc.z = acc.z * corr + p * v4.z;
        acc.w = acc.w * corr + p * v4.w;
        m = m_new;
    }

    // cross-warp merge
    if (lane == 0) { sm_m[warp] = m; sm_l[warp] = l; }
    sm_acc[warp][lane] = acc;
    __syncthreads();

    if (warp == 0) {
        float gm = -INFINITY;
        #pragma unroll
        for (int w = 0; w < NWARP; w++) gm = fmaxf(gm, sm_m[w]);
        float  gl = 0.f;
        float4 ga = make_float4(0.f, 0.f, 0.f, 0.f);
        #pragma unroll
        for (int w = 0; w < NWARP; w++) {
            const float c = __expf(sm_m[w] - gm);   // 0 for empty warps (m=-inf)
            gl += sm_l[w] * c;
            float4 a = sm_acc[w][lane];
            ga.x += a.x * c; ga.y += a.y * c; ga.z += a.z * c; ga.w += a.w * c;
        }
        const float invl = 1.0f / gl;
        float4 r = ((const float4*)(hidden + b * HIDDEN + h * HDIM))[lane];
        float4 o;
        o.x = r.x + ga.x * invl;
        o.y = r.y + ga.y * invl;
        o.z = r.z + ga.z * invl;
        o.w = r.w + ga.w * invl;
        ((float4*)(out + b * HIDDEN + h * HDIM))[lane] = o;
    }
}

// ---------------------------------------------------------------------------
extern "C" void kernel_launch(void* const* d_in, const int* in_sizes, int n_in,
                              void* d_out, int out_size) {
    const float* hidden = (const float*)d_in[0];
    const float* kcache = (const float*)d_in[1];
    const float* vcache = (const float*)d_in[2];
    const int*   btab   = (const int*)  d_in[3];
    const int*   clen   = (const int*)  d_in[4];
    const float* rmsw   = (const float*)d_in[5];
    float* out = (float*)d_out;

    rmsnorm_kernel<<<BATCH, 256>>>(hidden, rmsw);
    attn_kernel<<<dim3(HEADS, BATCH), 256>>>(kcache, vcache, btab, clen, hidden, out);
}

// round 4
// speedup vs baseline: 1.2586x; 1.2586x over previous
#include <cuda_runtime.h>
#include <math.h>

#define BATCH   16
#define HEADS   32
#define HDIM    128
#define NBLK    1024
#define BLKSZ   16
#define MAXB    128
#define HIDDEN  (HEADS * HDIM)
#define EPS     1e-6f
#define SCALE   0.08838834764831845f   // 1/sqrt(128)
#define NWARP   8
#define NS      8                       // KV splits per (b,h)

// allocation-free scratch
__device__ float g_q[BATCH * HIDDEN];
__device__ float g_pm[BATCH * HEADS * NS];
__device__ float g_pl[BATCH * HEADS * NS];
__device__ float g_pacc[BATCH * HEADS * NS * HDIM];

// ---------------------------------------------------------------------------
// Kernel 1: RMSNorm  q = x * rsqrt(mean(x^2)+eps) * w
// ---------------------------------------------------------------------------
__global__ void rmsnorm_kernel(const float* __restrict__ x,
                               const float* __restrict__ w) {
    const int b = blockIdx.x;
    const float4* row = (const float4*)(x + b * HIDDEN);
    const float4* wt  = (const float4*)w;
    float4* qo = (float4*)(g_q + b * HIDDEN);

    float ss = 0.f;
    float4 v[4];
    #pragma unroll
    for (int i = 0; i < 4; i++) {
        v[i] = row[threadIdx.x + i * 256];
        ss += v[i].x * v[i].x + v[i].y * v[i].y + v[i].z * v[i].z + v[i].w * v[i].w;
    }
    #pragma unroll
    for (int o = 16; o; o >>= 1) ss += __shfl_xor_sync(~0u, ss, o);

    __shared__ float red[8];
    if ((threadIdx.x & 31) == 0) red[threadIdx.x >> 5] = ss;
    __syncthreads();
    if (threadIdx.x < 32) {
        float s = (threadIdx.x < 8) ? red[threadIdx.x] : 0.f;
        #pragma unroll
        for (int o = 4; o; o >>= 1) s += __shfl_xor_sync(~0u, s, o);
        if (threadIdx.x == 0) red[0] = s;
    }
    __syncthreads();
    const float inv = rsqrtf(red[0] * (1.0f / HIDDEN) + EPS);

    #pragma unroll
    for (int i = 0; i < 4; i++) {
        float4 g = wt[threadIdx.x + i * 256];
        float4 o;
        o.x = v[i].x * inv * g.x;
        o.y = v[i].y * inv * g.y;
        o.z = v[i].z * inv * g.z;
        o.w = v[i].w * inv * g.w;
        qo[threadIdx.x + i * 256] = o;
    }
}

// ---------------------------------------------------------------------------
// Kernel 2: split-KV paged flash-decode. One CTA = (head, batch, split).
// Split z handles tokens [z*chunk, min((z+1)*chunk, L)), chunk = ceil(L/NS).
// 8 warps stride tokens; lane l owns head-dim [4l, 4l+4) as float4.
// Writes unnormalized partial (m, l, acc) to global scratch.
// ---------------------------------------------------------------------------
__global__ __launch_bounds__(256, 4)
void attn_split_kernel(const float* __restrict__ kc,
                       const float* __restrict__ vc,
                       const int*   __restrict__ bt,
                       const int*   __restrict__ ctx) {
    const int h = blockIdx.x;
    const int b = blockIdx.y;
    const int z = blockIdx.z;
    const int tid  = threadIdx.x;
    const int lane = tid & 31;
    const int warp = tid >> 5;

    __shared__ float4 sq[HDIM / 4];
    __shared__ int    sbt[MAXB];
    __shared__ float  sm_m[NWARP], sm_l[NWARP];
    __shared__ float4 sm_acc[NWARP][HDIM / 4];

    if (tid < HDIM / 4) sq[tid] = ((const float4*)(g_q + b * HIDDEN + h * HDIM))[tid];
    if (tid < MAXB)     sbt[tid] = bt[b * MAXB + tid];
    __syncthreads();

    const int L     = ctx[b];
    const int chunk = (L + NS - 1) / NS;
    const int start = z * chunk;
    const int end   = min(start + chunk, L);
    const int pidx  = (b * HEADS + h) * NS + z;

    const float4 q4 = sq[lane];

    float  m = -INFINITY, l = 0.f;
    float4 acc = make_float4(0.f, 0.f, 0.f, 0.f);

    int s = start + warp;
    // 2 tokens/iter -> 4 independent LDG.128 in flight per warp
    for (; s + NWARP < end; s += 2 * NWARP) {
        const int sa = s, sb2 = s + NWARP;
        const size_t offa = (((size_t)sbt[sa  >> 4] * BLKSZ + (sa  & 15)) * HEADS + h) * HDIM;
        const size_t offb = (((size_t)sbt[sb2 >> 4] * BLKSZ + (sb2 & 15)) * HEADS + h) * HDIM;
        float4 ka = ((const float4*)(kc + offa))[lane];
        float4 kb = ((const float4*)(kc + offb))[lane];
        float4 va = ((const float4*)(vc + offa))[lane];
        float4 vb = ((const float4*)(vc + offb))[lane];

        float da = q4.x * ka.x + q4.y * ka.y + q4.z * ka.z + q4.w * ka.w;
        float db = q4.x * kb.x + q4.y * kb.y + q4.z * kb.z + q4.w * kb.w;
        #pragma unroll
        for (int o = 16; o; o >>= 1) {
            da += __shfl_xor_sync(~0u, da, o);
            db += __shfl_xor_sync(~0u, db, o);
        }
        const float s0 = da * SCALE;
        const float s1 = db * SCALE;

        const float m_new = fmaxf(m, fmaxf(s0, s1));
        const float corr  = __expf(m - m_new);
        const float p0    = __expf(s0 - m_new);
        const float p1    = __expf(s1 - m_new);
        l = l * corr + p0 + p1;
        acc.x = acc.x * corr + p0 * va.x + p1 * vb.x;
        acc.y = acc.y * corr + p0 * va.y + p1 * vb.y;
        acc.z = acc.z * corr + p0 * va.z + p1 * vb.z;
        acc.w = acc.w * corr + p0 * va.w + p1 * vb.w;
        m = m_new;
    }
    if (s < end) {
        const size_t off = (((size_t)sbt[s >> 4] * BLKSZ + (s & 15)) * HEADS + h) * HDIM;
        float4 k4 = ((const float4*)(kc + off))[lane];
        float4 v4 = ((const float4*)(vc + off))[lane];
        float d = q4.x * k4.x + q4.y * k4.y + q4.z * k4.z + q4.w * k4.w;
        #pragma unroll
        for (int o = 16; o; o >>= 1) d += __shfl_xor_sync(~0u, d, o);
        const float sc = d * SCALE;
        const float m_new = fmaxf(m, sc);
        const float corr  = __expf(m - m_new);
        const float p     = __expf(sc - m_new);
        l = l * corr + p;
        acc.x = acc.x * corr + p * v4.x;
        acc.y = acc.y * corr + p * v4.y;
        acc.z = acc.z * corr + p * v4.z;
        acc.w = acc.w * corr + p * v4.w;
        m = m_new;
    }

    // cross-warp merge
    if (lane == 0) { sm_m[warp] = m; sm_l[warp] = l; }
    sm_acc[warp][lane] = acc;
    __syncthreads();

    if (warp == 0) {
        float gm = -INFINITY;
        #pragma unroll
        for (int w = 0; w < NWARP; w++) gm = fmaxf(gm, sm_m[w]);

        float4* pacc = (float4*)(g_pacc + (size_t)pidx * HDIM);
        if (gm == -INFINITY) {                 // empty split
            if (lane == 0) { g_pm[pidx] = -INFINITY; g_pl[pidx] = 0.f; }
            pacc[lane] = make_float4(0.f, 0.f, 0.f, 0.f);
            return;
        }
        float  gl = 0.f;
        float4 ga = make_float4(0.f, 0.f, 0.f, 0.f);
        #pragma unroll
        for (int w = 0; w < NWARP; w++) {
            const float c = __expf(sm_m[w] - gm);
            gl += sm_l[w] * c;
            float4 a = sm_acc[w][lane];
            ga.x += a.x * c; ga.y += a.y * c; ga.z += a.z * c; ga.w += a.w * c;
        }
        if (lane == 0) { g_pm[pidx] = gm; g_pl[pidx] = gl; }
        pacc[lane] = ga;
    }
}

// ---------------------------------------------------------------------------
// Kernel 3: merge NS partials, normalize, add residual
// ---------------------------------------------------------------------------
__global__ void attn_reduce_kernel(const float* __restrict__ hidden,
                                   float*       __restrict__ out) {
    const int h = blockIdx.x;
    const int b = blockIdx.y;
    const int lane = threadIdx.x;       // 32 threads
    const int base = (b * HEADS + h) * NS;

    float gm = -INFINITY;
    #pragma unroll
    for (int zz = 0; zz < NS; zz++) gm = fmaxf(gm, g_pm[base + zz]);

    float  gl = 0.f;
    float4 ga = make_float4(0.f, 0.f, 0.f, 0.f);
    #pragma unroll
    for (int zz = 0; zz < NS; zz++) {
        const float c = __expf(g_pm[base + zz] - gm);
        gl += g_pl[base + zz] * c;
        float4 a = ((const float4*)(g_pacc + (size_t)(base + zz) * HDIM))[lane];
        ga.x += a.x * c; ga.y += a.y * c; ga.z += a.z * c; ga.w += a.w * c;
    }
    const float invl = 1.0f / gl;
    float4 r = ((const float4*)(hidden + b * HIDDEN + h * HDIM))[lane];
    float4 o;
    o.x = r.x + ga.x * invl;
    o.y = r.y + ga.y * invl;
    o.z = r.z + ga.z * invl;
    o.w = r.w + ga.w * invl;
    ((float4*)(out + b * HIDDEN + h * HDIM))[lane] = o;
}

// ---------------------------------------------------------------------------
extern "C" void kernel_launch(void* const* d_in, const int* in_sizes, int n_in,
                              void* d_out, int out_size) {
    const float* hidden = (const float*)d_in[0];
    const float* kcache = (const float*)d_in[1];
    const float* vcache = (const float*)d_in[2];
    const int*   btab   = (const int*)  d_in[3];
    const int*   clen   = (const int*)  d_in[4];
    const float* rmsw   = (const float*)d_in[5];
    float* out = (float*)d_out;

    rmsnorm_kernel<<<BATCH, 256>>>(hidden, rmsw);
    attn_split_kernel<<<dim3(HEADS, BATCH, NS), 256>>>(kcache, vcache, btab, clen);
    attn_reduce_kernel<<<dim3(HEADS, BATCH), 32>>>(hidden, out);
}

// round 5
// speedup vs baseline: 1.3270x; 1.0544x over previous
#include <cuda_runtime.h>
#include <math.h>

#define BATCH   16
#define HEADS   32
#define HDIM    128
#define NBLK    1024
#define BLKSZ   16
#define MAXB    128
#define HIDDEN  (HEADS * HDIM)
#define EPS     1e-6f
#define SCALE   0.08838834764831845f   // 1/sqrt(128)
#define NWARP   8
#define CHUNK   128                     // fixed tokens per split CTA
#define ZMAX    16                      // max splits: MAXB*BLKSZ / CHUNK

// allocation-free scratch
__device__ float g_q[BATCH * HIDDEN];
__device__ float g_pm[BATCH * HEADS * ZMAX];
__device__ float g_pl[BATCH * HEADS * ZMAX];
__device__ float g_pacc[BATCH * HEADS * ZMAX * HDIM];

// ---------------------------------------------------------------------------
// Kernel 1: RMSNorm  q = x * rsqrt(mean(x^2)+eps) * w   (1024 thr, 1 f4/thr)
// ---------------------------------------------------------------------------
__global__ __launch_bounds__(1024)
void rmsnorm_kernel(const float* __restrict__ x,
                    const float* __restrict__ w) {
    const int b = blockIdx.x;
    const float4* row = (const float4*)(x + b * HIDDEN);
    const float4* wt  = (const float4*)w;
    float4* qo = (float4*)(g_q + b * HIDDEN);

    float4 v = row[threadIdx.x];
    float ss = v.x * v.x + v.y * v.y + v.z * v.z + v.w * v.w;
    #pragma unroll
    for (int o = 16; o; o >>= 1) ss += __shfl_xor_sync(~0u, ss, o);

    __shared__ float red[32];
    if ((threadIdx.x & 31) == 0) red[threadIdx.x >> 5] = ss;
    __syncthreads();
    if (threadIdx.x < 32) {
        float s = red[threadIdx.x];
        #pragma unroll
        for (int o = 16; o; o >>= 1) s += __shfl_xor_sync(~0u, s, o);
        if (threadIdx.x == 0) red[0] = s;
    }
    __syncthreads();
    const float inv = rsqrtf(red[0] * (1.0f / HIDDEN) + EPS);

    float4 g = wt[threadIdx.x];
    float4 o;
    o.x = v.x * inv * g.x;
    o.y = v.y * inv * g.y;
    o.z = v.z * inv * g.z;
    o.w = v.w * inv * g.w;
    qo[threadIdx.x] = o;
}

// ---------------------------------------------------------------------------
// Kernel 2: split-KV paged flash-decode, FIXED 128-token chunks.
// CTA = (head, batch, z); handles tokens [z*128, min(z*128+128, L)).
// Launched with PDL: K/V setup overlaps the tail of rmsnorm; grid-dep sync
// guards only the g_q read.
// ---------------------------------------------------------------------------
__global__ __launch_bounds__(256, 4)
void attn_split_kernel(const float* __restrict__ kc,
                       const float* __restrict__ vc,
                       const int*   __restrict__ bt,
                       const int*   __restrict__ ctx) {
    const int h = blockIdx.x;
    const int b = blockIdx.y;
    const int z = blockIdx.z;
    const int tid  = threadIdx.x;
    const int lane = tid & 31;
    const int warp = tid >> 5;

    const int L     = ctx[b];
    const int start = z * CHUNK;
    if (start >= L) return;                       // inactive split: exit fast
    const int end   = min(start + CHUNK, L);
    const int pidx  = (b * HEADS + h) * ZMAX + z;

    __shared__ float4 sq[HDIM / 4];
    __shared__ int    sbt[MAXB];
    __shared__ float  sm_m[NWARP], sm_l[NWARP];
    __shared__ float4 sm_acc[NWARP][HDIM / 4];

    // independent work first: block table (8 entries cover this 128-tok chunk)
    int btr = 0;
    if (tid < MAXB) btr = bt[b * MAXB + tid];

    // wait for rmsnorm's g_q only now
    cudaGridDependencySynchronize();

    if (tid < HDIM / 4) sq[tid] = ((const float4*)(g_q + b * HIDDEN + h * HDIM))[tid];
    if (tid < MAXB)     sbt[tid] = btr;
    __syncthreads();

    const float4 q4 = sq[lane];

    float  m = -INFINITY, l = 0.f;
    float4 acc = make_float4(0.f, 0.f, 0.f, 0.f);

    int s = start + warp;
    // 2 tokens/iter -> 4 independent LDG.128 in flight per warp
    for (; s + NWARP < end; s += 2 * NWARP) {
        const int sa = s, sb2 = s + NWARP;
        const size_t offa = (((size_t)sbt[sa  >> 4] * BLKSZ + (sa  & 15)) * HEADS + h) * HDIM;
        const size_t offb = (((size_t)sbt[sb2 >> 4] * BLKSZ + (sb2 & 15)) * HEADS + h) * HDIM;
        float4 ka = ((const float4*)(kc + offa))[lane];
        float4 kb = ((const float4*)(kc + offb))[lane];
        float4 va = ((const float4*)(vc + offa))[lane];
        float4 vb = ((const float4*)(vc + offb))[lane];

        float da = q4.x * ka.x + q4.y * ka.y + q4.z * ka.z + q4.w * ka.w;
        float db = q4.x * kb.x + q4.y * kb.y + q4.z * kb.z + q4.w * kb.w;
        #pragma unroll
        for (int o = 16; o; o >>= 1) {
            da += __shfl_xor_sync(~0u, da, o);
            db += __shfl_xor_sync(~0u, db, o);
        }
        const float s0 = da * SCALE;
        const float s1 = db * SCALE;

        const float m_new = fmaxf(m, fmaxf(s0, s1));
        const float corr  = __expf(m - m_new);
        const float p0    = __expf(s0 - m_new);
        const float p1    = __expf(s1 - m_new);
        l = l * corr + p0 + p1;
        acc.x = acc.x * corr + p0 * va.x + p1 * vb.x;
        acc.y = acc.y * corr + p0 * va.y + p1 * vb.y;
        acc.z = acc.z * corr + p0 * va.z + p1 * vb.z;
        acc.w = acc.w * corr + p0 * va.w + p1 * vb.w;
        m = m_new;
    }
    if (s < end) {
        const size_t off = (((size_t)sbt[s >> 4] * BLKSZ + (s & 15)) * HEADS + h) * HDIM;
        float4 k4 = ((const float4*)(kc + off))[lane];
        float4 v4 = ((const float4*)(vc + off))[lane];
        float d = q4.x * k4.x + q4.y * k4.y + q4.z * k4.z + q4.w * k4.w;
        #pragma unroll
        for (int o = 16; o; o >>= 1) d += __shfl_xor_sync(~0u, d, o);
        const float sc = d * SCALE;
        const float m_new = fmaxf(m, sc);
        const float corr  = __expf(m - m_new);
        const float p     = __expf(sc - m_new);
        l = l * corr + p;
        acc.x = acc.x * corr + p * v4.x;
        acc.y = acc.y * corr + p * v4.y;
        acc.z = acc.z * corr + p * v4.z;
        acc.w = acc.w * corr + p * v4.w;
        m = m_new;
    }

    // cross-warp merge (active splits have >=1 token in warp 0's range only
    // when end-start < NWARP; empty warps carry m=-inf and contribute c=0)
    if (lane == 0) { sm_m[warp] = m; sm_l[warp] = l; }
    sm_acc[warp][lane] = acc;
    __syncthreads();

    if (warp == 0) {
        float gm = -INFINITY;
        #pragma unroll
        for (int w = 0; w < NWARP; w++) gm = fmaxf(gm, sm_m[w]);
        float  gl = 0.f;
        float4 ga = make_float4(0.f, 0.f, 0.f, 0.f);
        #pragma unroll
        for (int w = 0; w < NWARP; w++) {
            const float c = __expf(sm_m[w] - gm);   // 0 for empty warps
            gl += sm_l[w] * c;
            float4 a = sm_acc[w][lane];
            ga.x += a.x * c; ga.y += a.y * c; ga.z += a.z * c; ga.w += a.w * c;
        }
        if (lane == 0) { g_pm[pidx] = gm; g_pl[pidx] = gl; }
        ((float4*)(g_pacc + (size_t)pidx * HDIM))[lane] = ga;
    }
}

// ---------------------------------------------------------------------------
// Kernel 3: merge active partials, normalize, add residual (PDL-launched)
// ---------------------------------------------------------------------------
__global__ void attn_reduce_kernel(const float* __restrict__ hidden,
                                   const int*   __restrict__ ctx,
                                   float*       __restrict__ out) {
    const int h = blockIdx.x;
    const int b = blockIdx.y;
    const int lane = threadIdx.x;       // 32 threads
    const int base = (b * HEADS + h) * ZMAX;

    // independent reads first
    const int   L  = ctx[b];
    const int   nz = (L + CHUNK - 1) / CHUNK;
    float4 r = ((const float4*)(hidden + b * HIDDEN + h * HDIM))[lane];

    cudaGridDependencySynchronize();    // wait for attn partials

    float gm = -INFINITY;
    for (int zz = 0; zz < nz; zz++) gm = fmaxf(gm, g_pm[base + zz]);

    float  gl = 0.f;
    float4 ga = make_float4(0.f, 0.f, 0.f, 0.f);
    for (int zz = 0; zz < nz; zz++) {
        const float c = __expf(g_pm[base + zz] - gm);
        gl += g_pl[base + zz] * c;
        float4 a = ((const float4*)(g_pacc + (size_t)(base + zz) * HDIM))[lane];
        ga.x += a.x * c; ga.y += a.y * c; ga.z += a.z * c; ga.w += a.w * c;
    }
    const float invl = 1.0f / gl;
    float4 o;
    o.x = r.x + ga.x * invl;
    o.y = r.y + ga.y * invl;
    o.z = r.z + ga.z * invl;
    o.w = r.w + ga.w * invl;
    ((float4*)(out + b * HIDDEN + h * HDIM))[lane] = o;
}

// ---------------------------------------------------------------------------
extern "C" void kernel_launch(void* const* d_in, const int* in_sizes, int n_in,
                              void* d_out, int out_size) {
    const float* hidden = (const float*)d_in[0];
    const float* kcache = (const float*)d_in[1];
    const float* vcache = (const float*)d_in[2];
    const int*   btab   = (const int*)  d_in[3];
    const int*   clen   = (const int*)  d_in[4];
    const float* rmsw   = (const float*)d_in[5];
    float* out = (float*)d_out;

    rmsnorm_kernel<<<BATCH, 1024>>>(hidden, rmsw);

    // attn: PDL so its setup overlaps rmsnorm's tail
    {
        cudaLaunchConfig_t cfg = {};
        cfg.gridDim  = dim3(HEADS, BATCH, ZMAX);
        cfg.blockDim = dim3(256);
        cudaLaunchAttribute at[1];
        at[0].id = cudaLaunchAttributeProgrammaticStreamSerialization;
        at[0].val.programmaticStreamSerializationAllowed = 1;
        cfg.attrs = at;
        cfg.numAttrs = 1;
        cfg.stream = 0;
        cudaLaunchKernelEx(&cfg, attn_split_kernel, kcache, vcache, btab, clen);
    }

    // reduce: PDL so residual/ctx loads overlap attn's tail
    {
        cudaLaunchConfig_t cfg = {};
        cfg.gridDim  = dim3(HEADS, BATCH);
        cfg.blockDim = dim3(32);
        cudaLaunchAttribute at[1];
        at[0].id = cudaLaunchAttributeProgrammaticStreamSerialization;
        at[0].val.programmaticStreamSerializationAllowed = 1;
        cfg.attrs = at;
        cfg.numAttrs = 1;
        cfg.stream = 0;
        cudaLaunchKernelEx(&cfg, attn_reduce_kernel, hidden, clen, out);
    }
}

// round 6
// speedup vs baseline: 1.3275x; 1.0004x over previous
#include <cuda_runtime.h>
#include <math.h>

#define BATCH   16
#define HEADS   32
#define HDIM    128
#define NBLK    1024
#define BLKSZ   16
#define MAXB    128
#define HIDDEN  (HEADS * HDIM)
#define EPS     1e-6f
#define SCALE   0.08838834764831845f   // 1/sqrt(128)
#define NWARP   8
#define CHUNK   128                     // fixed tokens per split CTA
#define ZMAX    16                      // max splits: MAXB*BLKSZ / CHUNK

// allocation-free scratch
__device__ float g_pm[BATCH * HEADS * ZMAX];
__device__ float g_pl[BATCH * HEADS * ZMAX];
__device__ float g_pacc[BATCH * HEADS * ZMAX * HDIM];

// ---------------------------------------------------------------------------
// Kernel 1: split-KV paged flash-decode with FUSED RMSNorm prologue.
// CTA = (head, batch, z); handles tokens [z*128, min(z*128+128, L)).
// Each CTA redundantly computes its batch's RMS statistic from the (L2-hot)
// hidden row, then normalizes its own 128-float q slice. No predecessor
// kernel -> zero serial dependency at the front.
// ---------------------------------------------------------------------------
__global__ __launch_bounds__(256, 4)
void attn_split_kernel(const float* __restrict__ kc,
                       const float* __restrict__ vc,
                       const int*   __restrict__ bt,
                       const int*   __restrict__ ctx,
                       const float* __restrict__ hidden,
                       const float* __restrict__ rmsw) {
    const int h = blockIdx.x;
    const int b = blockIdx.y;
    const int z = blockIdx.z;
    const int tid  = threadIdx.x;
    const int lane = tid & 31;
    const int warp = tid >> 5;

    const int L     = ctx[b];
    const int start = z * CHUNK;
    if (start >= L) return;                       // inactive split: exit fast
    const int end   = min(start + CHUNK, L);
    const int pidx  = (b * HEADS + h) * ZMAX + z;

    __shared__ float4 sq[HDIM / 4];
    __shared__ int    sbt[MAXB];
    __shared__ float  red[NWARP];
    __shared__ float  sm_m[NWARP], sm_l[NWARP];
    __shared__ float4 sm_acc[NWARP][HDIM / 4];

    // ---- fused RMSNorm prologue -------------------------------------------
    // sum of squares over the full hidden row of batch b (4096 floats)
    const float4* hrow = (const float4*)(hidden + b * HIDDEN);
    float ss = 0.f;
    #pragma unroll
    for (int i = 0; i < 4; i++) {
        float4 v = hrow[tid + i * 256];
        ss += v.x * v.x + v.y * v.y + v.z * v.z + v.w * v.w;
    }
    // block table load (independent)
    int btr = 0;
    if (tid < MAXB) btr = bt[b * MAXB + tid];

    #pragma unroll
    for (int o = 16; o; o >>= 1) ss += __shfl_xor_sync(~0u, ss, o);
    if (lane == 0) red[warp] = ss;
    if (tid < MAXB) sbt[tid] = btr;
    __syncthreads();
    if (tid < 32) {
        float s = (tid < NWARP) ? red[tid] : 0.f;
        #pragma unroll
        for (int o = 4; o; o >>= 1) s += __shfl_xor_sync(~0u, s, o);
        if (tid == 0) red[0] = s;
    }
    __syncthreads();
    const float inv = rsqrtf(red[0] * (1.0f / HIDDEN) + EPS);
    // normalize this head's q slice into smem
    if (tid < HDIM / 4) {
        float4 v = ((const float4*)(hidden + b * HIDDEN + h * HDIM))[tid];
        float4 g = ((const float4*)rmsw)[h * (HDIM / 4) + tid];
        float4 o;
        o.x = v.x * inv * g.x;
        o.y = v.y * inv * g.y;
        o.z = v.z * inv * g.z;
        o.w = v.w * inv * g.w;
        sq[tid] = o;
    }
    __syncthreads();
    // -----------------------------------------------------------------------

    const float4 q4 = sq[lane];

    float  m = -INFINITY, l = 0.f;
    float4 acc = make_float4(0.f, 0.f, 0.f, 0.f);

    int s = start + warp;
    // 2 tokens/iter -> 4 independent LDG.128 in flight per warp
    for (; s + NWARP < end; s += 2 * NWARP) {
        const int sa = s, sb2 = s + NWARP;
        const size_t offa = (((size_t)sbt[sa  >> 4] * BLKSZ + (sa  & 15)) * HEADS + h) * HDIM;
        const size_t offb = (((size_t)sbt[sb2 >> 4] * BLKSZ + (sb2 & 15)) * HEADS + h) * HDIM;
        float4 ka = ((const float4*)(kc + offa))[lane];
        float4 kb = ((const float4*)(kc + offb))[lane];
        float4 va = ((const float4*)(vc + offa))[lane];
        float4 vb = ((const float4*)(vc + offb))[lane];

        float da = q4.x * ka.x + q4.y * ka.y + q4.z * ka.z + q4.w * ka.w;
        float db = q4.x * kb.x + q4.y * kb.y + q4.z * kb.z + q4.w * kb.w;
        #pragma unroll
        for (int o = 16; o; o >>= 1) {
            da += __shfl_xor_sync(~0u, da, o);
            db += __shfl_xor_sync(~0u, db, o);
        }
        const float s0 = da * SCALE;
        const float s1 = db * SCALE;

        const float m_new = fmaxf(m, fmaxf(s0, s1));
        const float corr  = __expf(m - m_new);
        const float p0    = __expf(s0 - m_new);
        const float p1    = __expf(s1 - m_new);
        l = l * corr + p0 + p1;
        acc.x = acc.x * corr + p0 * va.x + p1 * vb.x;
        acc.y = acc.y * corr + p0 * va.y + p1 * vb.y;
        acc.z = acc.z * corr + p0 * va.z + p1 * vb.z;
        acc.w = acc.w * corr + p0 * va.w + p1 * vb.w;
        m = m_new;
    }
    if (s < end) {
        const size_t off = (((size_t)sbt[s >> 4] * BLKSZ + (s & 15)) * HEADS + h) * HDIM;
        float4 k4 = ((const float4*)(kc + off))[lane];
        float4 v4 = ((const float4*)(vc + off))[lane];
        float d = q4.x * k4.x + q4.y * k4.y + q4.z * k4.z + q4.w * k4.w;
        #pragma unroll
        for (int o = 16; o; o >>= 1) d += __shfl_xor_sync(~0u, d, o);
        const float sc = d * SCALE;
        const float m_new = fmaxf(m, sc);
        const float corr  = __expf(m - m_new);
        const float p     = __expf(sc - m_new);
        l = l * corr + p;
        acc.x = acc.x * corr + p * v4.x;
        acc.y = acc.y * corr + p * v4.y;
        acc.z = acc.z * corr + p * v4.z;
        acc.w = acc.w * corr + p * v4.w;
        m = m_new;
    }

    // cross-warp merge (empty warps carry m=-inf and contribute c=0)
    if (lane == 0) { sm_m[warp] = m; sm_l[warp] = l; }
    sm_acc[warp][lane] = acc;
    __syncthreads();

    if (warp == 0) {
        float gm = -INFINITY;
        #pragma unroll
        for (int w = 0; w < NWARP; w++) gm = fmaxf(gm, sm_m[w]);
        float  gl = 0.f;
        float4 ga = make_float4(0.f, 0.f, 0.f, 0.f);
        #pragma unroll
        for (int w = 0; w < NWARP; w++) {
            const float c = __expf(sm_m[w] - gm);
            gl += sm_l[w] * c;
            float4 a = sm_acc[w][lane];
            ga.x += a.x * c; ga.y += a.y * c; ga.z += a.z * c; ga.w += a.w * c;
        }
        if (lane == 0) { g_pm[pidx] = gm; g_pl[pidx] = gl; }
        ((float4*)(g_pacc + (size_t)pidx * HDIM))[lane] = ga;
    }
}

// ---------------------------------------------------------------------------
// Kernel 2: merge active partials, normalize, add residual (PDL-launched).
// 128 threads = 4 heads per CTA.
// ---------------------------------------------------------------------------
__global__ __launch_bounds__(128)
void attn_reduce_kernel(const float* __restrict__ hidden,
                        const int*   __restrict__ ctx,
                        float*       __restrict__ out) {
    const int h = blockIdx.x * 4 + (threadIdx.x >> 5);
    const int b = blockIdx.y;
    const int lane = threadIdx.x & 31;
    const int base = (b * HEADS + h) * ZMAX;

    // independent reads first
    const int   L  = ctx[b];
    const int   nz = (L + CHUNK - 1) / CHUNK;
    float4 r = ((const float4*)(hidden + b * HIDDEN + h * HDIM))[lane];

    cudaGridDependencySynchronize();    // wait for attn partials

    float gm = -INFINITY;
    for (int zz = 0; zz < nz; zz++) gm = fmaxf(gm, g_pm[base + zz]);

    float  gl = 0.f;
    float4 ga = make_float4(0.f, 0.f, 0.f, 0.f);
    for (int zz = 0; zz < nz; zz++) {
        const float c = __expf(g_pm[base + zz] - gm);
        gl += g_pl[base + zz] * c;
        float4 a = ((const float4*)(g_pacc + (size_t)(base + zz) * HDIM))[lane];
        ga.x += a.x * c; ga.y += a.y * c; ga.z += a.z * c; ga.w += a.w * c;
    }
    const float invl = 1.0f / gl;
    float4 o;
    o.x = r.x + ga.x * invl;
    o.y = r.y + ga.y * invl;
    o.z = r.z + ga.z * invl;
    o.w = r.w + ga.w * invl;
    ((float4*)(out + b * HIDDEN + h * HDIM))[lane] = o;
}

// ---------------------------------------------------------------------------
extern "C" void kernel_launch(void* const* d_in, const int* in_sizes, int n_in,
                              void* d_out, int out_size) {
    const float* hidden = (const float*)d_in[0];
    const float* kcache = (const float*)d_in[1];
    const float* vcache = (const float*)d_in[2];
    const int*   btab   = (const int*)  d_in[3];
    const int*   clen   = (const int*)  d_in[4];
    const float* rmsw   = (const float*)d_in[5];
    float* out = (float*)d_out;

    attn_split_kernel<<<dim3(HEADS, BATCH, ZMAX), 256>>>(
        kcache, vcache, btab, clen, hidden, rmsw);

    // reduce: PDL so residual/ctx loads overlap attn's tail
    {
        cudaLaunchConfig_t cfg = {};
        cfg.gridDim  = dim3(HEADS / 4, BATCH);
        cfg.blockDim = dim3(128);
        cudaLaunchAttribute at[1];
        at[0].id = cudaLaunchAttributeProgrammaticStreamSerialization;
        at[0].val.programmaticStreamSerializationAllowed = 1;
        cfg.attrs = at;
        cfg.numAttrs = 1;
        cfg.stream = 0;
        cudaLaunchKernelEx(&cfg, attn_reduce_kernel, hidden, clen, out);
    }
}